// round 16
// baseline (speedup 1.0000x reference)
#include <cuda_runtime.h>
#include <cuda_bf16.h>
#include <math.h>
#include <stdint.h>

#define EMBD   256
#define HEADS  16
#define DHEAD  16
#define BATCH  64
#define MROWS  128
#define JJOBS  512
#define TTOK   513
#define OUT_PER_B (MROWS * TTOK)   // 65664

#define XJOBS   32832
#define XMACH0  32896
#define XROWS   41088

typedef unsigned long long ull;

__device__ float g_O [BATCH * MROWS * EMBD];
__device__ float g_MH[BATCH * MROWS * EMBD];
__device__ float g_SUM[BATCH];
__device__ __nv_bfloat16 g_Xh[(long)XROWS * EMBD];
__device__ __nv_bfloat16 g_Xl[(long)XROWS * EMBD];
__device__ __nv_bfloat16 g_Wh[3 * EMBD * EMBD];   // [z][n][k]
__device__ __nv_bfloat16 g_Wl[3 * EMBD * EMBD];
__device__ __nv_bfloat16 g_MHh[BATCH * MROWS * EMBD];
__device__ __nv_bfloat16 g_MHl[BATCH * MROWS * EMBD];
__device__ __nv_bfloat16 g_Kh[(long)BATCH * TTOK * EMBD];
__device__ __nv_bfloat16 g_Kl[(long)BATCH * TTOK * EMBD];
__device__ __nv_bfloat16 g_Vh[(long)BATCH * TTOK * EMBD];
__device__ __nv_bfloat16 g_Vl[(long)BATCH * TTOK * EMBD];
__device__ __nv_bfloat16 g_Qh[BATCH * MROWS * EMBD];
__device__ __nv_bfloat16 g_Ql[BATCH * MROWS * EMBD];

// ---------------- packed f32x2 helpers ----------------
__device__ __forceinline__ ull fma2(ull a, ull b, ull c) {
    ull d; asm("fma.rn.f32x2 %0, %1, %2, %3;" : "=l"(d) : "l"(a), "l"(b), "l"(c));
    return d;
}
__device__ __forceinline__ ull bcast2(float x) {
    ull d; asm("mov.b64 %0, {%1, %2};" : "=l"(d) : "f"(x), "f"(x));
    return d;
}
__device__ __forceinline__ float2 unpack2(ull v) {
    float2 f; asm("mov.b64 {%0, %1}, %2;" : "=f"(f.x), "=f"(f.y) : "l"(v));
    return f;
}
__device__ __forceinline__ float tanh_fast(float x) {
    const float e = __expf(2.0f * x);
    return 1.0f - __fdividef(2.0f, e + 1.0f);
}

__device__ __forceinline__ const float* jobs_row(const float* __restrict__ jobs,
                                                 const float* __restrict__ skip,
                                                 int b, int t) {
    return (t == 0) ? skip : jobs + ((long)b * JJOBS + (t - 1)) * EMBD;
}

// mma.sync m16n8k16 row.col bf16 -> f32
__device__ __forceinline__ void mma_bf16(float* c, const uint32_t* a,
                                         uint32_t b0, uint32_t b1) {
    asm volatile(
        "mma.sync.aligned.m16n8k16.row.col.f32.bf16.bf16.f32 "
        "{%0,%1,%2,%3}, {%4,%5,%6,%7}, {%8,%9}, {%0,%1,%2,%3};"
        : "+f"(c[0]), "+f"(c[1]), "+f"(c[2]), "+f"(c[3])
        : "r"(a[0]), "r"(a[1]), "r"(a[2]), "r"(a[3]), "r"(b0), "r"(b1));
}

__device__ __forceinline__ uint32_t packbf(__nv_bfloat16 a, __nv_bfloat16 b) {
    __nv_bfloat162 t; t.x = a; t.y = b;
    return *(uint32_t*)&t;
}
__device__ __forceinline__ void split2(float x, float y,
                                       uint32_t& hi, uint32_t& lo) {
    const __nv_bfloat16 hx = __float2bfloat16_rn(x);
    const __nv_bfloat16 hy = __float2bfloat16_rn(y);
    const __nv_bfloat16 lx = __float2bfloat16_rn(x - __bfloat162float(hx));
    const __nv_bfloat16 ly = __float2bfloat16_rn(y - __bfloat162float(hy));
    hi = packbf(hx, hy);
    lo = packbf(lx, ly);
}
// reconstruct fp32 pair from hi/lo packed bf16
__device__ __forceinline__ float2 join2(uint32_t hi, uint32_t lo) {
    const __nv_bfloat162 h = *(const __nv_bfloat162*)&hi;
    const __nv_bfloat162 l = *(const __nv_bfloat162*)&lo;
    return make_float2(__bfloat162float(h.x) + __bfloat162float(l.x),
                       __bfloat162float(h.y) + __bfloat162float(l.y));
}

// =================== convert W -> bf16 hi/lo, transposed to [N][K] =========
__global__ void __launch_bounds__(256)
convert_w_kernel(const float* __restrict__ Wk, const float* __restrict__ Wv,
                 const float* __restrict__ Wq,
                 __nv_bfloat16* __restrict__ Wh, __nv_bfloat16* __restrict__ Wl)
{
    __shared__ float tile[32][33];
    const int z = blockIdx.z;
    const float* W = (z == 0) ? Wk : (z == 1) ? Wv : Wq;
    const int kb = blockIdx.y * 32;
    const int nb = blockIdx.x * 32;
    const int tx = threadIdx.x & 31;
    const int ty = threadIdx.x >> 5;

    #pragma unroll
    for (int i = 0; i < 32; i += 8)
        tile[ty + i][tx] = W[(long)(kb + ty + i) * EMBD + nb + tx];
    __syncthreads();
    #pragma unroll
    for (int i = 0; i < 32; i += 8) {
        const int n = nb + ty + i;
        const int k = kb + tx;
        const float w = tile[tx][ty + i];
        const __nv_bfloat16 hi = __float2bfloat16_rn(w);
        const __nv_bfloat16 lo = __float2bfloat16_rn(w - __bfloat162float(hi));
        const long idx = (long)z * EMBD * EMBD + (long)n * EMBD + k;
        Wh[idx] = hi;
        Wl[idx] = lo;
    }
}

// =================== convert X -> bf16 hi/lo ======
__global__ void __launch_bounds__(256)
convert_x_kernel(const float* __restrict__ jobs, const float* __restrict__ skip,
                 const float* __restrict__ machine,
                 __nv_bfloat16* __restrict__ Xh, __nv_bfloat16* __restrict__ Xl,
                 float* __restrict__ sums)
{
    if (blockIdx.x == 0 && threadIdx.x < BATCH) sums[threadIdx.x] = 0.0f;

    const long gid = (long)blockIdx.x * 256 + threadIdx.x;
    const long total = (long)XROWS * 32;
    if (gid >= total) return;
    const int row = (int)(gid >> 5);
    const int seg = ((int)gid & 31) * 8;

    float v[8] = {};
    const float* src = nullptr;
    if (row < XJOBS) {
        const int b = row / TTOK;
        const int t = row - b * TTOK;
        src = jobs_row(jobs, skip, b, t);
    } else if (row >= XMACH0) {
        src = machine + (long)(row - XMACH0) * EMBD;
    }
    if (src) {
        float4 a = *(const float4*)(src + seg);
        float4 c = *(const float4*)(src + seg + 4);
        v[0]=a.x; v[1]=a.y; v[2]=a.z; v[3]=a.w;
        v[4]=c.x; v[5]=c.y; v[6]=c.z; v[7]=c.w;
    }
    __nv_bfloat16 h[8], l[8];
    #pragma unroll
    for (int i = 0; i < 8; i++) {
        h[i] = __float2bfloat16_rn(v[i]);
        l[i] = __float2bfloat16_rn(v[i] - __bfloat162float(h[i]));
    }
    const long o = (long)row * EMBD + seg;
    *(uint4*)(Xh + o) = *(const uint4*)h;
    *(uint4*)(Xl + o) = *(const uint4*)l;
}

// =================== HMMA projection GEMM -> split bf16 outputs ============
#define PADK   72
#define TILE_B (128 * PADK * 2)
#define OFF_AH 0
#define OFF_AL (TILE_B)
#define OFF_BH (2 * TILE_B)
#define OFF_BL (3 * TILE_B)
#define PROJ_SMEM (4 * TILE_B)

__global__ void __launch_bounds__(256, 2)
proj_wmma_kernel(const __nv_bfloat16* __restrict__ Xh,
                 const __nv_bfloat16* __restrict__ Xl,
                 const __nv_bfloat16* __restrict__ Wh,
                 const __nv_bfloat16* __restrict__ Wl,
                 __nv_bfloat16* __restrict__ Kh, __nv_bfloat16* __restrict__ Kl,
                 __nv_bfloat16* __restrict__ Vh, __nv_bfloat16* __restrict__ Vl,
                 __nv_bfloat16* __restrict__ Qh, __nv_bfloat16* __restrict__ Ql)
{
    extern __shared__ char smem[];
    const int z = blockIdx.z;
    const int row_tiles = (z == 2) ? 64 : 257;
    if ((int)blockIdx.y >= row_tiles) return;

    const int tid  = threadIdx.x;
    const int warp = tid >> 5;
    const int lane = tid & 31;
    const int wm = warp & 3;
    const int wn = warp >> 2;
    const int g   = lane >> 2;
    const int tig = lane & 3;

    const int xrow0 = blockIdx.y * 128 + ((z == 2) ? XMACH0 : 0);
    const int col0  = blockIdx.x * 128;
    const int crow0 = blockIdx.y * 128;
    const int cvalid = (z == 2) ? (BATCH * MROWS) : XJOBS;
    __nv_bfloat16* Ch = (z == 0) ? Kh : (z == 1) ? Vh : Qh;
    __nv_bfloat16* Cl = (z == 0) ? Kl : (z == 1) ? Vl : Ql;

    const __nv_bfloat16* Wz = Wh + (long)z * EMBD * EMBD;
    const __nv_bfloat16* Wzl = Wl + (long)z * EMBD * EMBD;

    const int lrow = tid >> 1;
    const int lseg = (tid & 1) * 32;

    float acc[2][8][4] = {};

    #pragma unroll 1
    for (int kc = 0; kc < 4; kc++) {
        const int ko0 = kc * 64;
        {
            const __nv_bfloat16* gAh = Xh + (long)(xrow0 + lrow) * EMBD + ko0 + lseg;
            const __nv_bfloat16* gAl = Xl + (long)(xrow0 + lrow) * EMBD + ko0 + lseg;
            const __nv_bfloat16* gBh = Wz  + (long)(col0 + lrow) * EMBD + ko0 + lseg;
            const __nv_bfloat16* gBl = Wzl + (long)(col0 + lrow) * EMBD + ko0 + lseg;
            char* sAh = smem + OFF_AH + lrow * (PADK * 2) + lseg * 2;
            char* sAl = smem + OFF_AL + lrow * (PADK * 2) + lseg * 2;
            char* sBh = smem + OFF_BH + lrow * (PADK * 2) + lseg * 2;
            char* sBl = smem + OFF_BL + lrow * (PADK * 2) + lseg * 2;
            #pragma unroll
            for (int j = 0; j < 4; j++) {
                *(uint4*)(sAh + j * 16) = *(const uint4*)(gAh + j * 8);
                *(uint4*)(sAl + j * 16) = *(const uint4*)(gAl + j * 8);
                *(uint4*)(sBh + j * 16) = *(const uint4*)(gBh + j * 8);
                *(uint4*)(sBl + j * 16) = *(const uint4*)(gBl + j * 8);
            }
        }
        __syncthreads();

        #pragma unroll
        for (int ks = 0; ks < 4; ks++) {
            const int ko = ks * 16;
            uint32_t ahf[2][4], alf[2][4];
            #pragma unroll
            for (int mt = 0; mt < 2; mt++) {
                const int r0 = wm * 32 + mt * 16 + g;
                const char* bAh = smem + OFF_AH;
                const char* bAl = smem + OFF_AL;
                const int c0 = (ko + 2 * tig) * 2;
                const int c8 = (ko + 8 + 2 * tig) * 2;
                ahf[mt][0] = *(const uint32_t*)(bAh + r0 * (PADK*2) + c0);
                ahf[mt][1] = *(const uint32_t*)(bAh + (r0+8) * (PADK*2) + c0);
                ahf[mt][2] = *(const uint32_t*)(bAh + r0 * (PADK*2) + c8);
                ahf[mt][3] = *(const uint32_t*)(bAh + (r0+8) * (PADK*2) + c8);
                alf[mt][0] = *(const uint32_t*)(bAl + r0 * (PADK*2) + c0);
                alf[mt][1] = *(const uint32_t*)(bAl + (r0+8) * (PADK*2) + c0);
                alf[mt][2] = *(const uint32_t*)(bAl + r0 * (PADK*2) + c8);
                alf[mt][3] = *(const uint32_t*)(bAl + (r0+8) * (PADK*2) + c8);
            }
            #pragma unroll
            for (int nt = 0; nt < 8; nt++) {
                const int nr = wn * 64 + nt * 8 + g;
                const char* bBh = smem + OFF_BH;
                const char* bBl = smem + OFF_BL;
                const int c0 = (ko + 2 * tig) * 2;
                const int c8 = (ko + 8 + 2 * tig) * 2;
                const uint32_t bh0 = *(const uint32_t*)(bBh + nr * (PADK*2) + c0);
                const uint32_t bh1 = *(const uint32_t*)(bBh + nr * (PADK*2) + c8);
                const uint32_t bl0 = *(const uint32_t*)(bBl + nr * (PADK*2) + c0);
                const uint32_t bl1 = *(const uint32_t*)(bBl + nr * (PADK*2) + c8);
                #pragma unroll
                for (int mt = 0; mt < 2; mt++) {
                    mma_bf16(acc[mt][nt], ahf[mt], bh0, bh1);
                    mma_bf16(acc[mt][nt], ahf[mt], bl0, bl1);
                    mma_bf16(acc[mt][nt], alf[mt], bh0, bh1);
                }
            }
        }
        __syncthreads();
    }

    #pragma unroll
    for (int mt = 0; mt < 2; mt++) {
        const int r_lo = crow0 + wm * 32 + mt * 16 + g;
        const int r_hi = r_lo + 8;
        #pragma unroll
        for (int nt = 0; nt < 8; nt++) {
            const int col = col0 + wn * 64 + nt * 8 + 2 * tig;
            uint32_t h, l;
            if (r_lo < cvalid) {
                split2(acc[mt][nt][0], acc[mt][nt][1], h, l);
                *(uint32_t*)(Ch + (long)r_lo * EMBD + col) = h;
                *(uint32_t*)(Cl + (long)r_lo * EMBD + col) = l;
            }
            if (r_hi < cvalid) {
                split2(acc[mt][nt][2], acc[mt][nt][3], h, l);
                *(uint32_t*)(Ch + (long)r_hi * EMBD + col) = h;
                *(uint32_t*)(Cl + (long)r_hi * EMBD + col) = l;
            }
        }
    }
}

// =================== HMMA flash attention (all-bf16 inputs) ================
#define VTP 140
#define KPAD 24    // 48B rows: 16B-aligned stores, conflict-free frag loads
__global__ void __launch_bounds__(128)
attn_kernel(const __nv_bfloat16* __restrict__ Qh, const __nv_bfloat16* __restrict__ Ql,
            const __nv_bfloat16* __restrict__ Kh, const __nv_bfloat16* __restrict__ Kl,
            const __nv_bfloat16* __restrict__ Vh, const __nv_bfloat16* __restrict__ Vl,
            float* __restrict__ O)
{
    __shared__ __nv_bfloat16 Vth[16][VTP];
    __shared__ __nv_bfloat16 Vtl[16][VTP];
    __shared__ __nv_bfloat16 Ksh[128][KPAD];
    __shared__ __nv_bfloat16 Ksl[128][KPAD];

    const int h = blockIdx.x;
    const int b = blockIdx.y;
    const int tid = threadIdx.x;
    const int lane = tid & 31;
    const int warp = tid >> 5;
    const int g = lane >> 2;
    const int tig = lane & 3;
    const int r0 = warp * 32;

    // Q fragments: direct uint32 loads
    uint32_t qh[2][4], ql[2][4];
    #pragma unroll
    for (int mt = 0; mt < 2; mt++) {
        const int rA = r0 + mt * 16 + g;
        const int rB = rA + 8;
        const long oA = ((long)b * MROWS + rA) * EMBD + h * DHEAD;
        const long oB = ((long)b * MROWS + rB) * EMBD + h * DHEAD;
        qh[mt][0] = *(const uint32_t*)(Qh + oA + 2 * tig);
        qh[mt][1] = *(const uint32_t*)(Qh + oB + 2 * tig);
        qh[mt][2] = *(const uint32_t*)(Qh + oA + 8 + 2 * tig);
        qh[mt][3] = *(const uint32_t*)(Qh + oB + 8 + 2 * tig);
        ql[mt][0] = *(const uint32_t*)(Ql + oA + 2 * tig);
        ql[mt][1] = *(const uint32_t*)(Ql + oB + 2 * tig);
        ql[mt][2] = *(const uint32_t*)(Ql + oA + 8 + 2 * tig);
        ql[mt][3] = *(const uint32_t*)(Ql + oB + 8 + 2 * tig);
    }

    float accO[2][2][4] = {};
    float lsum[2][2] = {};

    #pragma unroll 1
    for (int c = 0; c < 4; c++) {
        const int t0 = c * 128;
        __syncthreads();
        // stage V^T hi/lo: thread (d = tid>>3, i = tid&7), 16 tokens
        {
            const int d = tid >> 3;
            const int i = tid & 7;
            const long base = ((long)b * TTOK + t0 + i * 16) * EMBD + h * DHEAD + d;
            #pragma unroll
            for (int jj = 0; jj < 16; jj += 2) {
                const __nv_bfloat16 h0 = Vh[base + (long)jj * EMBD];
                const __nv_bfloat16 h1 = Vh[base + (long)(jj + 1) * EMBD];
                const __nv_bfloat16 l0 = Vl[base + (long)jj * EMBD];
                const __nv_bfloat16 l1 = Vl[base + (long)(jj + 1) * EMBD];
                *(uint32_t*)&Vth[d][i * 16 + jj] = packbf(h0, h1);
                *(uint32_t*)&Vtl[d][i * 16 + jj] = packbf(l0, l1);
            }
        }
        // stage K rows hi/lo: plain uint4 copies (token = tid)
        {
            const long base = ((long)b * TTOK + t0 + tid) * EMBD + h * DHEAD;
            *(uint4*)&Ksh[tid][0] = *(const uint4*)(Kh + base);
            *(uint4*)&Ksh[tid][8] = *(const uint4*)(Kh + base + 8);
            *(uint4*)&Ksl[tid][0] = *(const uint4*)(Kl + base);
            *(uint4*)&Ksl[tid][8] = *(const uint4*)(Kl + base + 8);
        }
        __syncthreads();

        #pragma unroll 1
        for (int ntp = 0; ntp < 8; ntp++) {
            uint32_t kh[2][2], kl[2][2];
            #pragma unroll
            for (int half = 0; half < 2; half++) {
                const int tok = (2 * ntp + half) * 8 + g;
                kh[half][0] = *(const uint32_t*)&Ksh[tok][2 * tig];
                kh[half][1] = *(const uint32_t*)&Ksh[tok][8 + 2 * tig];
                kl[half][0] = *(const uint32_t*)&Ksl[tok][2 * tig];
                kl[half][1] = *(const uint32_t*)&Ksl[tok][8 + 2 * tig];
            }
            #pragma unroll
            for (int mt = 0; mt < 2; mt++) {
                uint32_t ph[4], pl[4];
                #pragma unroll
                for (int half = 0; half < 2; half++) {
                    float s[4] = {0.f, 0.f, 0.f, 0.f};
                    mma_bf16(s, qh[mt], kh[half][0], kh[half][1]);
                    mma_bf16(s, qh[mt], kl[half][0], kl[half][1]);
                    mma_bf16(s, ql[mt], kh[half][0], kh[half][1]);
                    const float p0 = __expf(s[0] * 0.25f);
                    const float p1 = __expf(s[1] * 0.25f);
                    const float p2 = __expf(s[2] * 0.25f);
                    const float p3 = __expf(s[3] * 0.25f);
                    lsum[mt][0] += p0 + p1;
                    lsum[mt][1] += p2 + p3;
                    split2(p0, p1, ph[half * 2 + 0], pl[half * 2 + 0]);
                    split2(p2, p3, ph[half * 2 + 1], pl[half * 2 + 1]);
                }
                #pragma unroll
                for (int dn = 0; dn < 2; dn++) {
                    const int vr = 8 * dn + g;
                    const uint32_t vh0 = *(const uint32_t*)&Vth[vr][ntp * 16 + 2 * tig];
                    const uint32_t vh1 = *(const uint32_t*)&Vth[vr][ntp * 16 + 8 + 2 * tig];
                    const uint32_t vl0 = *(const uint32_t*)&Vtl[vr][ntp * 16 + 2 * tig];
                    const uint32_t vl1 = *(const uint32_t*)&Vtl[vr][ntp * 16 + 8 + 2 * tig];
                    mma_bf16(accO[mt][dn], ph, vh0, vh1);
                    mma_bf16(accO[mt][dn], ph, vl0, vl1);
                    mma_bf16(accO[mt][dn], pl, vh0, vh1);
                }
            }
        }
    }

    #pragma unroll
    for (int mt = 0; mt < 2; mt++) {
        #pragma unroll
        for (int j = 0; j < 2; j++) {
            float v = lsum[mt][j];
            v += __shfl_xor_sync(0xFFFFFFFFu, v, 1);
            v += __shfl_xor_sync(0xFFFFFFFFu, v, 2);
            lsum[mt][j] = v;
        }
    }

    // tail token t = 512 (reconstruct fp32 from hi+lo)
    {
        const long kb = ((long)b * TTOK + 512) * EMBD + h * DHEAD;
        const float2 k0 = join2(*(const uint32_t*)(Kh + kb + 2 * tig),
                                *(const uint32_t*)(Kl + kb + 2 * tig));
        const float2 k1 = join2(*(const uint32_t*)(Kh + kb + 8 + 2 * tig),
                                *(const uint32_t*)(Kl + kb + 8 + 2 * tig));
        #pragma unroll
        for (int mt = 0; mt < 2; mt++) {
            const float2 qa0 = join2(qh[mt][0], ql[mt][0]);
            const float2 qb0 = join2(qh[mt][1], ql[mt][1]);
            const float2 qa1 = join2(qh[mt][2], ql[mt][2]);
            const float2 qb1 = join2(qh[mt][3], ql[mt][3]);
            float dA = qa0.x * k0.x + qa0.y * k0.y + qa1.x * k1.x + qa1.y * k1.y;
            float dB = qb0.x * k0.x + qb0.y * k0.y + qb1.x * k1.x + qb1.y * k1.y;
            dA += __shfl_xor_sync(0xFFFFFFFFu, dA, 1);
            dA += __shfl_xor_sync(0xFFFFFFFFu, dA, 2);
            dB += __shfl_xor_sync(0xFFFFFFFFu, dB, 1);
            dB += __shfl_xor_sync(0xFFFFFFFFu, dB, 2);
            const float pA = __expf(dA * 0.25f);
            const float pB = __expf(dB * 0.25f);
            lsum[mt][0] += pA;
            lsum[mt][1] += pB;
            #pragma unroll
            for (int dn = 0; dn < 2; dn++) {
                const float2 v = join2(
                    *(const uint32_t*)(Vh + kb + dn * 8 + 2 * tig),
                    *(const uint32_t*)(Vl + kb + dn * 8 + 2 * tig));
                accO[mt][dn][0] += pA * v.x;
                accO[mt][dn][1] += pA * v.y;
                accO[mt][dn][2] += pB * v.x;
                accO[mt][dn][3] += pB * v.y;
            }
        }
    }

    #pragma unroll
    for (int mt = 0; mt < 2; mt++) {
        const int rA = r0 + mt * 16 + g;
        const int rB = rA + 8;
        const float invA = 1.0f / lsum[mt][0];
        const float invB = 1.0f / lsum[mt][1];
        float* oa = O + ((long)b * MROWS + rA) * EMBD + h * DHEAD;
        float* ob = O + ((long)b * MROWS + rB) * EMBD + h * DHEAD;
        #pragma unroll
        for (int dn = 0; dn < 2; dn++) {
            *(float2*)(oa + dn * 8 + 2 * tig) =
                make_float2(accO[mt][dn][0] * invA, accO[mt][dn][1] * invA);
            *(float2*)(ob + dn * 8 + 2 * tig) =
                make_float2(accO[mt][dn][2] * invB, accO[mt][dn][3] * invB);
        }
    }
}

// =================== Wc projection (+bias) + MH bf16 split out ==============
#define BK 16
#define BN 128
#define WBM 64
__global__ void __launch_bounds__(256)
wc_kernel(const float* __restrict__ X, const float* __restrict__ W,
          const float* __restrict__ bias, float* __restrict__ C,
          __nv_bfloat16* __restrict__ MHh, __nv_bfloat16* __restrict__ MHl)
{
    __shared__ float As[2][BK][WBM + 4];
    __shared__ float Bs[2][BK][BN];

    const int tid  = threadIdx.x;
    const int row0 = blockIdx.y * WBM;
    const int col0 = blockIdx.x * BN;

    const int a_row = tid >> 2;
    const int a_k   = (tid & 3) * 4;
    const int b_k   = tid >> 4;
    const int b_n   = (tid & 15) * 8;
    const int tx = tid & 15;
    const int ty = tid >> 4;

    const float* xrow = X + (long)(row0 + a_row) * EMBD;
    const float* wptr = W + (long)b_k * EMBD + col0 + b_n;

    float4 av, bv0, bv1;
    av  = *(const float4*)(xrow + a_k);
    bv0 = *(const float4*)(wptr);
    bv1 = *(const float4*)(wptr + 4);
    As[0][a_k+0][a_row]=av.x; As[0][a_k+1][a_row]=av.y;
    As[0][a_k+2][a_row]=av.z; As[0][a_k+3][a_row]=av.w;
    *(float4*)&Bs[0][b_k][b_n]     = bv0;
    *(float4*)&Bs[0][b_k][b_n + 4] = bv1;
    __syncthreads();

    ull acc2[4][4] = {};

    #pragma unroll 1
    for (int ks = 0; ks < EMBD / BK; ks++) {
        const int cur = ks & 1;
        const bool has_next = (ks < EMBD / BK - 1);
        if (has_next) {
            const int k0 = (ks + 1) * BK;
            av  = *(const float4*)(xrow + k0 + a_k);
            bv0 = *(const float4*)(wptr + (long)k0 * EMBD);
            bv1 = *(const float4*)(wptr + (long)k0 * EMBD + 4);
        }
        #pragma unroll
        for (int kk = 0; kk < BK; kk++) {
            float4 a0 = *(const float4*)&As[cur][kk][ty * 4];
            ulonglong2 p0 = *(const ulonglong2*)&Bs[cur][kk][tx * 4];
            ulonglong2 p1 = *(const ulonglong2*)&Bs[cur][kk][64 + tx * 4];
            ull B2[4] = {p0.x, p0.y, p1.x, p1.y};
            float a[4] = {a0.x, a0.y, a0.z, a0.w};
            #pragma unroll
            for (int i = 0; i < 4; i++) {
                const ull ai = bcast2(a[i]);
                #pragma unroll
                for (int j = 0; j < 4; j++)
                    acc2[i][j] = fma2(ai, B2[j], acc2[i][j]);
            }
        }
        if (has_next) {
            const int nxt = 1 - cur;
            As[nxt][a_k+0][a_row]=av.x; As[nxt][a_k+1][a_row]=av.y;
            As[nxt][a_k+2][a_row]=av.z; As[nxt][a_k+3][a_row]=av.w;
            *(float4*)&Bs[nxt][b_k][b_n]     = bv0;
            *(float4*)&Bs[nxt][b_k][b_n + 4] = bv1;
        }
        __syncthreads();
    }

    float4 bb0 = *(const float4*)(bias + col0 + tx * 4);
    float4 bb1 = *(const float4*)(bias + col0 + 64 + tx * 4);

    #pragma unroll
    for (int i = 0; i < 4; i++) {
        const int r = row0 + ty * 4 + i;
        float2 c0 = unpack2(acc2[i][0]);
        float2 c1 = unpack2(acc2[i][1]);
        float2 c2 = unpack2(acc2[i][2]);
        float2 c3 = unpack2(acc2[i][3]);
        float4 o0 = make_float4(c0.x+bb0.x, c0.y+bb0.y, c1.x+bb0.z, c1.y+bb0.w);
        float4 o1 = make_float4(c2.x+bb1.x, c2.y+bb1.y, c3.x+bb1.z, c3.y+bb1.w);
        const long m0 = (long)r * EMBD + col0 + tx * 4;
        const long m1 = (long)r * EMBD + col0 + 64 + tx * 4;
        *(float4*)(C + m0) = o0;
        *(float4*)(C + m1) = o1;
        uint32_t h0, l0, h1, l1;
        split2(o0.x, o0.y, h0, l0); split2(o0.z, o0.w, h1, l1);
        *(uint32_t*)(MHh + m0) = h0; *(uint32_t*)(MHh + m0 + 2) = h1;
        *(uint32_t*)(MHl + m0) = l0; *(uint32_t*)(MHl + m0 + 2) = l1;
        split2(o1.x, o1.y, h0, l0); split2(o1.z, o1.w, h1, l1);
        *(uint32_t*)(MHh + m1) = h0; *(uint32_t*)(MHh + m1 + 2) = h1;
        *(uint32_t*)(MHl + m1) = l0; *(uint32_t*)(MHl + m1 + 2) = l1;
    }
}

// =================== score2: HMMA bf16-split + tanh/exp epilogue ===========
__global__ void __launch_bounds__(256, 2)
score2_kernel(const __nv_bfloat16* __restrict__ MHh,
              const __nv_bfloat16* __restrict__ MHl,
              const __nv_bfloat16* __restrict__ Xh,
              const __nv_bfloat16* __restrict__ Xl,
              const float* __restrict__ mask,
              float* __restrict__ out, float* __restrict__ sums)
{
    extern __shared__ char smem[];
    __shared__ float red[256];

    const int b    = blockIdx.z;
    const int col0 = blockIdx.x * 128;

    const int tid  = threadIdx.x;
    const int warp = tid >> 5;
    const int lane = tid & 31;
    const int wm = warp & 3;
    const int wn = warp >> 2;
    const int g   = lane >> 2;
    const int tig = lane & 3;

    const int lrow = tid >> 1;
    const int lseg = (tid & 1) * 32;

    float acc[2][8][4] = {};

    #pragma unroll 1
    for (int kc = 0; kc < 4; kc++) {
        const int ko0 = kc * 64;
        {
            const __nv_bfloat16* gAh = MHh + (long)(b * MROWS + lrow) * EMBD + ko0 + lseg;
            const __nv_bfloat16* gAl = MHl + (long)(b * MROWS + lrow) * EMBD + ko0 + lseg;
            const __nv_bfloat16* gBh = Xh + (long)(b * TTOK + col0 + lrow) * EMBD + ko0 + lseg;
            const __nv_bfloat16* gBl = Xl + (long)(b * TTOK + col0 + lrow) * EMBD + ko0 + lseg;
            char* sAh = smem + OFF_AH + lrow * (PADK * 2) + lseg * 2;
            char* sAl = smem + OFF_AL + lrow * (PADK * 2) + lseg * 2;
            char* sBh = smem + OFF_BH + lrow * (PADK * 2) + lseg * 2;
            char* sBl = smem + OFF_BL + lrow * (PADK * 2) + lseg * 2;
            #pragma unroll
            for (int j = 0; j < 4; j++) {
                *(uint4*)(sAh + j * 16) = *(const uint4*)(gAh + j * 8);
                *(uint4*)(sAl + j * 16) = *(const uint4*)(gAl + j * 8);
                *(uint4*)(sBh + j * 16) = *(const uint4*)(gBh + j * 8);
                *(uint4*)(sBl + j * 16) = *(const uint4*)(gBl + j * 8);
            }
        }
        __syncthreads();

        #pragma unroll
        for (int ks = 0; ks < 4; ks++) {
            const int ko = ks * 16;
            uint32_t ahf[2][4], alf[2][4];
            #pragma unroll
            for (int mt = 0; mt < 2; mt++) {
                const int r0 = wm * 32 + mt * 16 + g;
                const char* bAh = smem + OFF_AH;
                const char* bAl = smem + OFF_AL;
                const int c0 = (ko + 2 * tig) * 2;
                const int c8 = (ko + 8 + 2 * tig) * 2;
                ahf[mt][0] = *(const uint32_t*)(bAh + r0 * (PADK*2) + c0);
                ahf[mt][1] = *(const uint32_t*)(bAh + (r0+8) * (PADK*2) + c0);
                ahf[mt][2] = *(const uint32_t*)(bAh + r0 * (PADK*2) + c8);
                ahf[mt][3] = *(const uint32_t*)(bAh + (r0+8) * (PADK*2) + c8);
                alf[mt][0] = *(const uint32_t*)(bAl + r0 * (PADK*2) + c0);
                alf[mt][1] = *(const uint32_t*)(bAl + (r0+8) * (PADK*2) + c0);
                alf[mt][2] = *(const uint32_t*)(bAl + r0 * (PADK*2) + c8);
                alf[mt][3] = *(const uint32_t*)(bAl + (r0+8) * (PADK*2) + c8);
            }
            #pragma unroll
            for (int nt = 0; nt < 8; nt++) {
                const int nr = wn * 64 + nt * 8 + g;
                const char* bBh = smem + OFF_BH;
                const char* bBl = smem + OFF_BL;
                const int c0 = (ko + 2 * tig) * 2;
                const int c8 = (ko + 8 + 2 * tig) * 2;
                const uint32_t bh0 = *(const uint32_t*)(bBh + nr * (PADK*2) + c0);
                const uint32_t bh1 = *(const uint32_t*)(bBh + nr * (PADK*2) + c8);
                const uint32_t bl0 = *(const uint32_t*)(bBl + nr * (PADK*2) + c0);
                const uint32_t bl1 = *(const uint32_t*)(bBl + nr * (PADK*2) + c8);
                #pragma unroll
                for (int mt = 0; mt < 2; mt++) {
                    mma_bf16(acc[mt][nt], ahf[mt], bh0, bh1);
                    mma_bf16(acc[mt][nt], ahf[mt], bl0, bl1);
                    mma_bf16(acc[mt][nt], alf[mt], bh0, bh1);
                }
            }
        }
        __syncthreads();
    }

    float lsum = 0.0f;
    #pragma unroll
    for (int mt = 0; mt < 2; mt++) {
        const int r_lo = wm * 32 + mt * 16 + g;
        const int r_hi = r_lo + 8;
        const long base_lo = (long)b * OUT_PER_B + (long)r_lo * TTOK;
        const long base_hi = (long)b * OUT_PER_B + (long)r_hi * TTOK;
        #pragma unroll
        for (int nt = 0; nt < 8; nt++) {
            const int t = col0 + wn * 64 + nt * 8 + 2 * tig;
            const float y0 = __expf(10.0f * tanh_fast(acc[mt][nt][0] * 0.0625f) + mask[base_lo + t]);
            const float y1 = __expf(10.0f * tanh_fast(acc[mt][nt][1] * 0.0625f) + mask[base_lo + t + 1]);
            const float y2 = __expf(10.0f * tanh_fast(acc[mt][nt][2] * 0.0625f) + mask[base_hi + t]);
            const float y3 = __expf(10.0f * tanh_fast(acc[mt][nt][3] * 0.0625f) + mask[base_hi + t + 1]);
            out[base_lo + t]     = y0;
            out[base_lo + t + 1] = y1;
            out[base_hi + t]     = y2;
            out[base_hi + t + 1] = y3;
            lsum += y0 + y1 + y2 + y3;
        }
    }

    red[tid] = lsum;
    __syncthreads();
    #pragma unroll
    for (int s = 128; s > 0; s >>= 1) {
        if (tid < s) red[tid] += red[tid + s];
        __syncthreads();
    }
    if (tid == 0) atomicAdd(&sums[b], red[0]);
}

// =================== t=512 column tail ================
__global__ void __launch_bounds__(128)
tail_kernel(const float* __restrict__ MH, const float* __restrict__ jobs,
            const float* __restrict__ mask, float* __restrict__ out,
            float* __restrict__ sums)
{
    __shared__ float jrow[EMBD];
    __shared__ float red[128];

    const int b = blockIdx.x;
    const int m = threadIdx.x;

    const float* jr = jobs + ((long)b * JJOBS + 511) * EMBD;
    *(float2*)&jrow[m * 2] = *(const float2*)(jr + m * 2);
    __syncthreads();

    const float* mh = MH + ((long)b * MROWS + m) * EMBD;
    ull d2 = bcast2(0.0f);
    #pragma unroll
    for (int k = 0; k < EMBD; k += 8) {
        ulonglong2 a = *(const ulonglong2*)(mh + k);
        ulonglong2 a2 = *(const ulonglong2*)(mh + k + 4);
        ulonglong2 w = *(const ulonglong2*)&jrow[k];
        ulonglong2 w2 = *(const ulonglong2*)&jrow[k + 4];
        d2 = fma2(a.x, w.x, d2);
        d2 = fma2(a.y, w.y, d2);
        d2 = fma2(a2.x, w2.x, d2);
        d2 = fma2(a2.y, w2.y, d2);
    }
    float2 f = unpack2(d2);
    const float sc = (f.x + f.y) * 0.0625f;
    const long li = (long)b * OUT_PER_B + (long)m * TTOK + 512;
    const float y = __expf(10.0f * tanh_fast(sc) + mask[li]);
    out[li] = y;

    red[m] = y;
    __syncthreads();
    #pragma unroll
    for (int s = 64; s > 0; s >>= 1) {
        if (m < s) red[m] += red[m + s];
        __syncthreads();
    }
    if (m == 0) atomicAdd(&sums[b], red[0]);
}

// =================== normalize =======================
__global__ void __launch_bounds__(256)
norm_kernel(float4* __restrict__ out, const float* __restrict__ sums)
{
    const int b = blockIdx.y;
    const long per_b4 = OUT_PER_B / 4;
    const long idx = (long)blockIdx.x * blockDim.x + threadIdx.x;
    if (idx < per_b4) {
        const float inv = 1.0f / sums[b];
        float4 v = out[(long)b * per_b4 + idx];
        v.x *= inv; v.y *= inv; v.z *= inv; v.w *= inv;
        out[(long)b * per_b4 + idx] = v;
    }
}

// =================== launch ===================
extern "C" void kernel_launch(void* const* d_in, const int* in_sizes, int n_in,
                              void* d_out, int out_size)
{
    const float* machine = (const float*)d_in[0];
    const float* jobs    = (const float*)d_in[1];
    const float* mask    = (const float*)d_in[2];
    const float* Wq3     = (const float*)d_in[3];
    const float* Wk      = (const float*)d_in[4];
    const float* Wv      = (const float*)d_in[5];
    const float* Wc      = (const float*)d_in[6];
    const float* bc      = (const float*)d_in[7];
    const float* skip    = (const float*)d_in[8];
    float* out = (float*)d_out;

    float *Op, *MHp, *Sp;
    __nv_bfloat16 *Xh, *Xl, *Wh, *Wl, *MHh, *MHl;
    __nv_bfloat16 *Kh, *Kl, *Vh, *Vl, *Qh, *Ql;
    cudaGetSymbolAddress((void**)&Op,  g_O);
    cudaGetSymbolAddress((void**)&MHp, g_MH);
    cudaGetSymbolAddress((void**)&Sp,  g_SUM);
    cudaGetSymbolAddress((void**)&Xh,  g_Xh);
    cudaGetSymbolAddress((void**)&Xl,  g_Xl);
    cudaGetSymbolAddress((void**)&Wh,  g_Wh);
    cudaGetSymbolAddress((void**)&Wl,  g_Wl);
    cudaGetSymbolAddress((void**)&MHh, g_MHh);
    cudaGetSymbolAddress((void**)&MHl, g_MHl);
    cudaGetSymbolAddress((void**)&Kh,  g_Kh);
    cudaGetSymbolAddress((void**)&Kl,  g_Kl);
    cudaGetSymbolAddress((void**)&Vh,  g_Vh);
    cudaGetSymbolAddress((void**)&Vl,  g_Vl);
    cudaGetSymbolAddress((void**)&Qh,  g_Qh);
    cudaGetSymbolAddress((void**)&Ql,  g_Ql);

    cudaFuncSetAttribute(proj_wmma_kernel,
                         cudaFuncAttributeMaxDynamicSharedMemorySize, PROJ_SMEM);
    cudaFuncSetAttribute(score2_kernel,
                         cudaFuncAttributeMaxDynamicSharedMemorySize, PROJ_SMEM);

    convert_w_kernel<<<dim3(8, 8, 3), 256>>>(Wk, Wv, Wq3, Wh, Wl);
    {
        const long total = (long)XROWS * 32;
        convert_x_kernel<<<(int)((total + 255) / 256), 256>>>(
            jobs, skip, machine, Xh, Xl, Sp);
    }

    proj_wmma_kernel<<<dim3(2, 257, 3), 256, PROJ_SMEM>>>(
        Xh, Xl, Wh, Wl, Kh, Kl, Vh, Vl, Qh, Ql);

    attn_kernel<<<dim3(HEADS, BATCH), 128>>>(Qh, Ql, Kh, Kl, Vh, Vl, Op);

    wc_kernel<<<dim3(EMBD / BN, (BATCH * MROWS) / WBM), 256>>>(
        Op, Wc, bc, MHp, MHh, MHl);

    score2_kernel<<<dim3(4, 1, BATCH), 256, PROJ_SMEM>>>(
        MHh, MHl, Xh, Xl, mask, out, Sp);
    tail_kernel<<<BATCH, 128>>>(MHp, jobs, mask, out, Sp);

    const int per_b4 = OUT_PER_B / 4;
    norm_kernel<<<dim3((per_b4 + 255) / 256, BATCH), 256>>>((float4*)out, Sp);
}

// round 17
// speedup vs baseline: 1.0568x; 1.0568x over previous
#include <cuda_runtime.h>
#include <cuda_bf16.h>
#include <math.h>
#include <stdint.h>

#define EMBD   256
#define HEADS  16
#define DHEAD  16
#define BATCH  64
#define MROWS  128
#define JJOBS  512
#define TTOK   513
#define OUT_PER_B (MROWS * TTOK)   // 65664

#define XJOBS   32832
#define XMACH0  32896
#define XROWS   41088

typedef unsigned long long ull;

__device__ float g_Q [BATCH * MROWS * EMBD];
__device__ float g_K [BATCH * TTOK  * EMBD];
__device__ float g_V [BATCH * TTOK  * EMBD];
__device__ float g_O [BATCH * MROWS * EMBD];
__device__ float g_MH[BATCH * MROWS * EMBD];
__device__ float g_SUM[BATCH];
__device__ __nv_bfloat16 g_Xh[(long)XROWS * EMBD];
__device__ __nv_bfloat16 g_Xl[(long)XROWS * EMBD];
__device__ __nv_bfloat16 g_Wh[3 * EMBD * EMBD];   // [z][n][k]
__device__ __nv_bfloat16 g_Wl[3 * EMBD * EMBD];
__device__ __nv_bfloat16 g_MHh[BATCH * MROWS * EMBD];
__device__ __nv_bfloat16 g_MHl[BATCH * MROWS * EMBD];

// ---------------- packed f32x2 helpers ----------------
__device__ __forceinline__ ull fma2(ull a, ull b, ull c) {
    ull d; asm("fma.rn.f32x2 %0, %1, %2, %3;" : "=l"(d) : "l"(a), "l"(b), "l"(c));
    return d;
}
__device__ __forceinline__ ull bcast2(float x) {
    ull d; asm("mov.b64 %0, {%1, %2};" : "=l"(d) : "f"(x), "f"(x));
    return d;
}
__device__ __forceinline__ float2 unpack2(ull v) {
    float2 f; asm("mov.b64 {%0, %1}, %2;" : "=f"(f.x), "=f"(f.y) : "l"(v));
    return f;
}
__device__ __forceinline__ float tanh_fast(float x) {
    const float e = __expf(2.0f * x);
    return 1.0f - __fdividef(2.0f, e + 1.0f);
}

__device__ __forceinline__ const float* jobs_row(const float* __restrict__ jobs,
                                                 const float* __restrict__ skip,
                                                 int b, int t) {
    return (t == 0) ? skip : jobs + ((long)b * JJOBS + (t - 1)) * EMBD;
}

// mma.sync m16n8k16 row.col bf16 -> f32
__device__ __forceinline__ void mma_bf16(float* c, const uint32_t* a,
                                         uint32_t b0, uint32_t b1) {
    asm volatile(
        "mma.sync.aligned.m16n8k16.row.col.f32.bf16.bf16.f32 "
        "{%0,%1,%2,%3}, {%4,%5,%6,%7}, {%8,%9}, {%0,%1,%2,%3};"
        : "+f"(c[0]), "+f"(c[1]), "+f"(c[2]), "+f"(c[3])
        : "r"(a[0]), "r"(a[1]), "r"(a[2]), "r"(a[3]), "r"(b0), "r"(b1));
}

__device__ __forceinline__ uint32_t packbf(__nv_bfloat16 a, __nv_bfloat16 b) {
    __nv_bfloat162 t; t.x = a; t.y = b;
    return *(uint32_t*)&t;
}
__device__ __forceinline__ void split2(float x, float y,
                                       uint32_t& hi, uint32_t& lo) {
    const __nv_bfloat16 hx = __float2bfloat16_rn(x);
    const __nv_bfloat16 hy = __float2bfloat16_rn(y);
    const __nv_bfloat16 lx = __float2bfloat16_rn(x - __bfloat162float(hx));
    const __nv_bfloat16 ly = __float2bfloat16_rn(y - __bfloat162float(hy));
    hi = packbf(hx, hy);
    lo = packbf(lx, ly);
}

// =================== convert W -> bf16 hi/lo, transposed to [N][K] =========
__global__ void __launch_bounds__(256)
convert_w_kernel(const float* __restrict__ Wk, const float* __restrict__ Wv,
                 const float* __restrict__ Wq,
                 __nv_bfloat16* __restrict__ Wh, __nv_bfloat16* __restrict__ Wl)
{
    __shared__ float tile[32][33];
    const int z = blockIdx.z;
    const float* W = (z == 0) ? Wk : (z == 1) ? Wv : Wq;
    const int kb = blockIdx.y * 32;
    const int nb = blockIdx.x * 32;
    const int tx = threadIdx.x & 31;
    const int ty = threadIdx.x >> 5;

    #pragma unroll
    for (int i = 0; i < 32; i += 8)
        tile[ty + i][tx] = W[(long)(kb + ty + i) * EMBD + nb + tx];
    __syncthreads();
    #pragma unroll
    for (int i = 0; i < 32; i += 8) {
        const int n = nb + ty + i;
        const int k = kb + tx;
        const float w = tile[tx][ty + i];
        const __nv_bfloat16 hi = __float2bfloat16_rn(w);
        const __nv_bfloat16 lo = __float2bfloat16_rn(w - __bfloat162float(hi));
        const long idx = (long)z * EMBD * EMBD + (long)n * EMBD + k;
        Wh[idx] = hi;
        Wl[idx] = lo;
    }
}

// =================== convert X -> bf16 hi/lo ======
__global__ void __launch_bounds__(256)
convert_x_kernel(const float* __restrict__ jobs, const float* __restrict__ skip,
                 const float* __restrict__ machine,
                 __nv_bfloat16* __restrict__ Xh, __nv_bfloat16* __restrict__ Xl,
                 float* __restrict__ sums)
{
    if (blockIdx.x == 0 && threadIdx.x < BATCH) sums[threadIdx.x] = 0.0f;

    const long gid = (long)blockIdx.x * 256 + threadIdx.x;
    const long total = (long)XROWS * 32;
    if (gid >= total) return;
    const int row = (int)(gid >> 5);
    const int seg = ((int)gid & 31) * 8;

    float v[8] = {};
    const float* src = nullptr;
    if (row < XJOBS) {
        const int b = row / TTOK;
        const int t = row - b * TTOK;
        src = jobs_row(jobs, skip, b, t);
    } else if (row >= XMACH0) {
        src = machine + (long)(row - XMACH0) * EMBD;
    }
    if (src) {
        float4 a = *(const float4*)(src + seg);
        float4 c = *(const float4*)(src + seg + 4);
        v[0]=a.x; v[1]=a.y; v[2]=a.z; v[3]=a.w;
        v[4]=c.x; v[5]=c.y; v[6]=c.z; v[7]=c.w;
    }
    __nv_bfloat16 h[8], l[8];
    #pragma unroll
    for (int i = 0; i < 8; i++) {
        h[i] = __float2bfloat16_rn(v[i]);
        l[i] = __float2bfloat16_rn(v[i] - __bfloat162float(h[i]));
    }
    const long o = (long)row * EMBD + seg;
    *(uint4*)(Xh + o) = *(const uint4*)h;
    *(uint4*)(Xl + o) = *(const uint4*)l;
}

// =================== HMMA projection GEMM ==================================
#define PADK   72
#define TILE_B (128 * PADK * 2)
#define OFF_AH 0
#define OFF_AL (TILE_B)
#define OFF_BH (2 * TILE_B)
#define OFF_BL (3 * TILE_B)
#define PROJ_SMEM (4 * TILE_B)

__global__ void __launch_bounds__(256, 2)
proj_wmma_kernel(const __nv_bfloat16* __restrict__ Xh,
                 const __nv_bfloat16* __restrict__ Xl,
                 const __nv_bfloat16* __restrict__ Wh,
                 const __nv_bfloat16* __restrict__ Wl,
                 float* __restrict__ Kout, float* __restrict__ Vout,
                 float* __restrict__ Qout)
{
    extern __shared__ char smem[];
    const int z = blockIdx.z;
    const int row_tiles = (z == 2) ? 64 : 257;
    if ((int)blockIdx.y >= row_tiles) return;

    const int tid  = threadIdx.x;
    const int warp = tid >> 5;
    const int lane = tid & 31;
    const int wm = warp & 3;
    const int wn = warp >> 2;
    const int g   = lane >> 2;
    const int tig = lane & 3;

    const int xrow0 = blockIdx.y * 128 + ((z == 2) ? XMACH0 : 0);
    const int col0  = blockIdx.x * 128;
    const int crow0 = blockIdx.y * 128;
    const int cvalid = (z == 2) ? (BATCH * MROWS) : XJOBS;
    float* C = (z == 0) ? Kout : (z == 1) ? Vout : Qout;

    const __nv_bfloat16* Wz = Wh + (long)z * EMBD * EMBD;
    const __nv_bfloat16* Wzl = Wl + (long)z * EMBD * EMBD;

    const int lrow = tid >> 1;
    const int lseg = (tid & 1) * 32;

    float acc[2][8][4] = {};

    #pragma unroll 1
    for (int kc = 0; kc < 4; kc++) {
        const int ko0 = kc * 64;
        {
            const __nv_bfloat16* gAh = Xh + (long)(xrow0 + lrow) * EMBD + ko0 + lseg;
            const __nv_bfloat16* gAl = Xl + (long)(xrow0 + lrow) * EMBD + ko0 + lseg;
            const __nv_bfloat16* gBh = Wz  + (long)(col0 + lrow) * EMBD + ko0 + lseg;
            const __nv_bfloat16* gBl = Wzl + (long)(col0 + lrow) * EMBD + ko0 + lseg;
            char* sAh = smem + OFF_AH + lrow * (PADK * 2) + lseg * 2;
            char* sAl = smem + OFF_AL + lrow * (PADK * 2) + lseg * 2;
            char* sBh = smem + OFF_BH + lrow * (PADK * 2) + lseg * 2;
            char* sBl = smem + OFF_BL + lrow * (PADK * 2) + lseg * 2;
            #pragma unroll
            for (int j = 0; j < 4; j++) {
                *(uint4*)(sAh + j * 16) = *(const uint4*)(gAh + j * 8);
                *(uint4*)(sAl + j * 16) = *(const uint4*)(gAl + j * 8);
                *(uint4*)(sBh + j * 16) = *(const uint4*)(gBh + j * 8);
                *(uint4*)(sBl + j * 16) = *(const uint4*)(gBl + j * 8);
            }
        }
        __syncthreads();

        #pragma unroll
        for (int ks = 0; ks < 4; ks++) {
            const int ko = ks * 16;
            uint32_t ahf[2][4], alf[2][4];
            #pragma unroll
            for (int mt = 0; mt < 2; mt++) {
                const int r0 = wm * 32 + mt * 16 + g;
                const char* bAh = smem + OFF_AH;
                const char* bAl = smem + OFF_AL;
                const int c0 = (ko + 2 * tig) * 2;
                const int c8 = (ko + 8 + 2 * tig) * 2;
                ahf[mt][0] = *(const uint32_t*)(bAh + r0 * (PADK*2) + c0);
                ahf[mt][1] = *(const uint32_t*)(bAh + (r0+8) * (PADK*2) + c0);
                ahf[mt][2] = *(const uint32_t*)(bAh + r0 * (PADK*2) + c8);
                ahf[mt][3] = *(const uint32_t*)(bAh + (r0+8) * (PADK*2) + c8);
                alf[mt][0] = *(const uint32_t*)(bAl + r0 * (PADK*2) + c0);
                alf[mt][1] = *(const uint32_t*)(bAl + (r0+8) * (PADK*2) + c0);
                alf[mt][2] = *(const uint32_t*)(bAl + r0 * (PADK*2) + c8);
                alf[mt][3] = *(const uint32_t*)(bAl + (r0+8) * (PADK*2) + c8);
            }
            #pragma unroll
            for (int nt = 0; nt < 8; nt++) {
                const int nr = wn * 64 + nt * 8 + g;
                const char* bBh = smem + OFF_BH;
                const char* bBl = smem + OFF_BL;
                const int c0 = (ko + 2 * tig) * 2;
                const int c8 = (ko + 8 + 2 * tig) * 2;
                const uint32_t bh0 = *(const uint32_t*)(bBh + nr * (PADK*2) + c0);
                const uint32_t bh1 = *(const uint32_t*)(bBh + nr * (PADK*2) + c8);
                const uint32_t bl0 = *(const uint32_t*)(bBl + nr * (PADK*2) + c0);
                const uint32_t bl1 = *(const uint32_t*)(bBl + nr * (PADK*2) + c8);
                #pragma unroll
                for (int mt = 0; mt < 2; mt++) {
                    mma_bf16(acc[mt][nt], ahf[mt], bh0, bh1);
                    mma_bf16(acc[mt][nt], ahf[mt], bl0, bl1);
                    mma_bf16(acc[mt][nt], alf[mt], bh0, bh1);
                }
            }
        }
        __syncthreads();
    }

    #pragma unroll
    for (int mt = 0; mt < 2; mt++) {
        const int r_lo = crow0 + wm * 32 + mt * 16 + g;
        const int r_hi = r_lo + 8;
        #pragma unroll
        for (int nt = 0; nt < 8; nt++) {
            const int col = col0 + wn * 64 + nt * 8 + 2 * tig;
            if (r_lo < cvalid)
                *(float2*)(C + (long)r_lo * EMBD + col) =
                    make_float2(acc[mt][nt][0], acc[mt][nt][1]);
            if (r_hi < cvalid)
                *(float2*)(C + (long)r_hi * EMBD + col) =
                    make_float2(acc[mt][nt][2], acc[mt][nt][3]);
        }
    }
}

// =================== HMMA flash attention (K staged in smem) ===============
#define VTP 140
#define KPAD 18
__global__ void __launch_bounds__(128)
attn_kernel(const float* __restrict__ Q, const float* __restrict__ K,
            const float* __restrict__ V, float* __restrict__ O)
{
    __shared__ __nv_bfloat16 Vth[16][VTP];
    __shared__ __nv_bfloat16 Vtl[16][VTP];
    __shared__ __nv_bfloat16 Ksh[128][KPAD];
    __shared__ __nv_bfloat16 Ksl[128][KPAD];

    const int h = blockIdx.x;
    const int b = blockIdx.y;
    const int tid = threadIdx.x;
    const int lane = tid & 31;
    const int warp = tid >> 5;
    const int g = lane >> 2;
    const int tig = lane & 3;
    const int r0 = warp * 32;

    uint32_t qh[2][4], ql[2][4];
    #pragma unroll
    for (int mt = 0; mt < 2; mt++) {
        const int rA = r0 + mt * 16 + g;
        const int rB = rA + 8;
        const float* qa = Q + ((long)b * MROWS + rA) * EMBD + h * DHEAD;
        const float* qb = Q + ((long)b * MROWS + rB) * EMBD + h * DHEAD;
        float2 x0 = *(const float2*)(qa + 2 * tig);
        float2 x1 = *(const float2*)(qb + 2 * tig);
        float2 x2 = *(const float2*)(qa + 8 + 2 * tig);
        float2 x3 = *(const float2*)(qb + 8 + 2 * tig);
        split2(x0.x, x0.y, qh[mt][0], ql[mt][0]);
        split2(x1.x, x1.y, qh[mt][1], ql[mt][1]);
        split2(x2.x, x2.y, qh[mt][2], ql[mt][2]);
        split2(x3.x, x3.y, qh[mt][3], ql[mt][3]);
    }

    float accO[2][2][4] = {};
    float lsum[2][2] = {};

    #pragma unroll 1
    for (int c = 0; c < 4; c++) {
        const int t0 = c * 128;
        __syncthreads();
        // stage V^T hi/lo
        {
            const int d = tid >> 3;
            const int i = tid & 7;
            const float* vp = V + ((long)b * TTOK + t0 + i * 16) * EMBD
                              + h * DHEAD + d;
            #pragma unroll
            for (int jj = 0; jj < 16; jj += 2) {
                const float v0 = vp[(long)jj * EMBD];
                const float v1 = vp[(long)(jj + 1) * EMBD];
                uint32_t hi, lo;
                split2(v0, v1, hi, lo);
                *(uint32_t*)&Vth[d][i * 16 + jj] = hi;
                *(uint32_t*)&Vtl[d][i * 16 + jj] = lo;
            }
        }
        // stage K rows hi/lo (token = tid)
        {
            const float* kp = K + ((long)b * TTOK + t0 + tid) * EMBD + h * DHEAD;
            #pragma unroll
            for (int d = 0; d < 16; d += 2) {
                float2 kv = *(const float2*)(kp + d);
                uint32_t hi, lo;
                split2(kv.x, kv.y, hi, lo);
                *(uint32_t*)&Ksh[tid][d] = hi;
                *(uint32_t*)&Ksl[tid][d] = lo;
            }
        }
        __syncthreads();

        #pragma unroll 1
        for (int ntp = 0; ntp < 8; ntp++) {
            uint32_t kh[2][2], kl[2][2];
            #pragma unroll
            for (int half = 0; half < 2; half++) {
                const int tok = (2 * ntp + half) * 8 + g;
                kh[half][0] = *(const uint32_t*)&Ksh[tok][2 * tig];
                kh[half][1] = *(const uint32_t*)&Ksh[tok][8 + 2 * tig];
                kl[half][0] = *(const uint32_t*)&Ksl[tok][2 * tig];
                kl[half][1] = *(const uint32_t*)&Ksl[tok][8 + 2 * tig];
            }
            #pragma unroll
            for (int mt = 0; mt < 2; mt++) {
                uint32_t ph[4], pl[4];
                #pragma unroll
                for (int half = 0; half < 2; half++) {
                    float s[4] = {0.f, 0.f, 0.f, 0.f};
                    mma_bf16(s, qh[mt], kh[half][0], kh[half][1]);
                    mma_bf16(s, qh[mt], kl[half][0], kl[half][1]);
                    mma_bf16(s, ql[mt], kh[half][0], kh[half][1]);
                    const float p0 = __expf(s[0] * 0.25f);
                    const float p1 = __expf(s[1] * 0.25f);
                    const float p2 = __expf(s[2] * 0.25f);
                    const float p3 = __expf(s[3] * 0.25f);
                    lsum[mt][0] += p0 + p1;
                    lsum[mt][1] += p2 + p3;
                    split2(p0, p1, ph[half * 2 + 0], pl[half * 2 + 0]);
                    split2(p2, p3, ph[half * 2 + 1], pl[half * 2 + 1]);
                }
                #pragma unroll
                for (int dn = 0; dn < 2; dn++) {
                    const int vr = 8 * dn + g;
                    const uint32_t vh0 = *(const uint32_t*)&Vth[vr][ntp * 16 + 2 * tig];
                    const uint32_t vh1 = *(const uint32_t*)&Vth[vr][ntp * 16 + 8 + 2 * tig];
                    const uint32_t vl0 = *(const uint32_t*)&Vtl[vr][ntp * 16 + 2 * tig];
                    const uint32_t vl1 = *(const uint32_t*)&Vtl[vr][ntp * 16 + 8 + 2 * tig];
                    mma_bf16(accO[mt][dn], ph, vh0, vh1);
                    mma_bf16(accO[mt][dn], ph, vl0, vl1);
                    mma_bf16(accO[mt][dn], pl, vh0, vh1);
                }
            }
        }
    }

    #pragma unroll
    for (int mt = 0; mt < 2; mt++) {
        #pragma unroll
        for (int j = 0; j < 2; j++) {
            float v = lsum[mt][j];
            v += __shfl_xor_sync(0xFFFFFFFFu, v, 1);
            v += __shfl_xor_sync(0xFFFFFFFFu, v, 2);
            lsum[mt][j] = v;
        }
    }

    // tail token t = 512 (fp32 exact)
    {
        const float* kp = K + ((long)b * TTOK + 512) * EMBD + h * DHEAD;
        const float2 k0 = *(const float2*)(kp + 2 * tig);
        const float2 k1 = *(const float2*)(kp + 8 + 2 * tig);
        const float* vp = V + ((long)b * TTOK + 512) * EMBD + h * DHEAD;
        #pragma unroll
        for (int mt = 0; mt < 2; mt++) {
            const int rA = r0 + mt * 16 + g;
            const int rB = rA + 8;
            const float* qa = Q + ((long)b * MROWS + rA) * EMBD + h * DHEAD;
            const float* qb = Q + ((long)b * MROWS + rB) * EMBD + h * DHEAD;
            const float2 qa0 = *(const float2*)(qa + 2 * tig);
            const float2 qa1 = *(const float2*)(qa + 8 + 2 * tig);
            const float2 qb0 = *(const float2*)(qb + 2 * tig);
            const float2 qb1 = *(const float2*)(qb + 8 + 2 * tig);
            float dA = qa0.x * k0.x + qa0.y * k0.y + qa1.x * k1.x + qa1.y * k1.y;
            float dB = qb0.x * k0.x + qb0.y * k0.y + qb1.x * k1.x + qb1.y * k1.y;
            dA += __shfl_xor_sync(0xFFFFFFFFu, dA, 1);
            dA += __shfl_xor_sync(0xFFFFFFFFu, dA, 2);
            dB += __shfl_xor_sync(0xFFFFFFFFu, dB, 1);
            dB += __shfl_xor_sync(0xFFFFFFFFu, dB, 2);
            const float pA = __expf(dA * 0.25f);
            const float pB = __expf(dB * 0.25f);
            lsum[mt][0] += pA;
            lsum[mt][1] += pB;
            #pragma unroll
            for (int dn = 0; dn < 2; dn++) {
                const float2 v = *(const float2*)(vp + dn * 8 + 2 * tig);
                accO[mt][dn][0] += pA * v.x;
                accO[mt][dn][1] += pA * v.y;
                accO[mt][dn][2] += pB * v.x;
                accO[mt][dn][3] += pB * v.y;
            }
        }
    }

    #pragma unroll
    for (int mt = 0; mt < 2; mt++) {
        const int rA = r0 + mt * 16 + g;
        const int rB = rA + 8;
        const float invA = 1.0f / lsum[mt][0];
        const float invB = 1.0f / lsum[mt][1];
        float* oa = O + ((long)b * MROWS + rA) * EMBD + h * DHEAD;
        float* ob = O + ((long)b * MROWS + rB) * EMBD + h * DHEAD;
        #pragma unroll
        for (int dn = 0; dn < 2; dn++) {
            *(float2*)(oa + dn * 8 + 2 * tig) =
                make_float2(accO[mt][dn][0] * invA, accO[mt][dn][1] * invA);
            *(float2*)(ob + dn * 8 + 2 * tig) =
                make_float2(accO[mt][dn][2] * invB, accO[mt][dn][3] * invB);
        }
    }
}

// =================== Wc projection (+bias) + MH bf16 split out ==============
#define BK 16
#define BN 128
#define WBM 64
__global__ void __launch_bounds__(256)
wc_kernel(const float* __restrict__ X, const float* __restrict__ W,
          const float* __restrict__ bias, float* __restrict__ C,
          __nv_bfloat16* __restrict__ MHh, __nv_bfloat16* __restrict__ MHl)
{
    __shared__ float As[2][BK][WBM + 4];
    __shared__ float Bs[2][BK][BN];

    const int tid  = threadIdx.x;
    const int row0 = blockIdx.y * WBM;
    const int col0 = blockIdx.x * BN;

    const int a_row = tid >> 2;
    const int a_k   = (tid & 3) * 4;
    const int b_k   = tid >> 4;
    const int b_n   = (tid & 15) * 8;
    const int tx = tid & 15;
    const int ty = tid >> 4;

    const float* xrow = X + (long)(row0 + a_row) * EMBD;
    const float* wptr = W + (long)b_k * EMBD + col0 + b_n;

    float4 av, bv0, bv1;
    av  = *(const float4*)(xrow + a_k);
    bv0 = *(const float4*)(wptr);
    bv1 = *(const float4*)(wptr + 4);
    As[0][a_k+0][a_row]=av.x; As[0][a_k+1][a_row]=av.y;
    As[0][a_k+2][a_row]=av.z; As[0][a_k+3][a_row]=av.w;
    *(float4*)&Bs[0][b_k][b_n]     = bv0;
    *(float4*)&Bs[0][b_k][b_n + 4] = bv1;
    __syncthreads();

    ull acc2[4][4] = {};

    #pragma unroll 1
    for (int ks = 0; ks < EMBD / BK; ks++) {
        const int cur = ks & 1;
        const bool has_next = (ks < EMBD / BK - 1);
        if (has_next) {
            const int k0 = (ks + 1) * BK;
            av  = *(const float4*)(xrow + k0 + a_k);
            bv0 = *(const float4*)(wptr + (long)k0 * EMBD);
            bv1 = *(const float4*)(wptr + (long)k0 * EMBD + 4);
        }
        #pragma unroll
        for (int kk = 0; kk < BK; kk++) {
            float4 a0 = *(const float4*)&As[cur][kk][ty * 4];
            ulonglong2 p0 = *(const ulonglong2*)&Bs[cur][kk][tx * 4];
            ulonglong2 p1 = *(const ulonglong2*)&Bs[cur][kk][64 + tx * 4];
            ull B2[4] = {p0.x, p0.y, p1.x, p1.y};
            float a[4] = {a0.x, a0.y, a0.z, a0.w};
            #pragma unroll
            for (int i = 0; i < 4; i++) {
                const ull ai = bcast2(a[i]);
                #pragma unroll
                for (int j = 0; j < 4; j++)
                    acc2[i][j] = fma2(ai, B2[j], acc2[i][j]);
            }
        }
        if (has_next) {
            const int nxt = 1 - cur;
            As[nxt][a_k+0][a_row]=av.x; As[nxt][a_k+1][a_row]=av.y;
            As[nxt][a_k+2][a_row]=av.z; As[nxt][a_k+3][a_row]=av.w;
            *(float4*)&Bs[nxt][b_k][b_n]     = bv0;
            *(float4*)&Bs[nxt][b_k][b_n + 4] = bv1;
        }
        __syncthreads();
    }

    float4 bb0 = *(const float4*)(bias + col0 + tx * 4);
    float4 bb1 = *(const float4*)(bias + col0 + 64 + tx * 4);

    #pragma unroll
    for (int i = 0; i < 4; i++) {
        const int r = row0 + ty * 4 + i;
        float2 c0 = unpack2(acc2[i][0]);
        float2 c1 = unpack2(acc2[i][1]);
        float2 c2 = unpack2(acc2[i][2]);
        float2 c3 = unpack2(acc2[i][3]);
        float4 o0 = make_float4(c0.x+bb0.x, c0.y+bb0.y, c1.x+bb0.z, c1.y+bb0.w);
        float4 o1 = make_float4(c2.x+bb1.x, c2.y+bb1.y, c3.x+bb1.z, c3.y+bb1.w);
        const long m0 = (long)r * EMBD + col0 + tx * 4;
        const long m1 = (long)r * EMBD + col0 + 64 + tx * 4;
        *(float4*)(C + m0) = o0;
        *(float4*)(C + m1) = o1;
        uint32_t h0, l0, h1, l1;
        split2(o0.x, o0.y, h0, l0); split2(o0.z, o0.w, h1, l1);
        *(uint32_t*)(MHh + m0) = h0; *(uint32_t*)(MHh + m0 + 2) = h1;
        *(uint32_t*)(MHl + m0) = l0; *(uint32_t*)(MHl + m0 + 2) = l1;
        split2(o1.x, o1.y, h0, l0); split2(o1.z, o1.w, h1, l1);
        *(uint32_t*)(MHh + m1) = h0; *(uint32_t*)(MHh + m1 + 2) = h1;
        *(uint32_t*)(MHl + m1) = l0; *(uint32_t*)(MHl + m1 + 2) = l1;
    }
}

// =================== score2: HMMA bf16-split + tanh/exp epilogue ===========
__global__ void __launch_bounds__(256, 2)
score2_kernel(const __nv_bfloat16* __restrict__ MHh,
              const __nv_bfloat16* __restrict__ MHl,
              const __nv_bfloat16* __restrict__ Xh,
              const __nv_bfloat16* __restrict__ Xl,
              const float* __restrict__ mask,
              float* __restrict__ out, float* __restrict__ sums)
{
    extern __shared__ char smem[];
    __shared__ float red[256];

    const int b    = blockIdx.z;
    const int col0 = blockIdx.x * 128;

    const int tid  = threadIdx.x;
    const int warp = tid >> 5;
    const int lane = tid & 31;
    const int wm = warp & 3;
    const int wn = warp >> 2;
    const int g   = lane >> 2;
    const int tig = lane & 3;

    const int lrow = tid >> 1;
    const int lseg = (tid & 1) * 32;

    float acc[2][8][4] = {};

    #pragma unroll 1
    for (int kc = 0; kc < 4; kc++) {
        const int ko0 = kc * 64;
        {
            const __nv_bfloat16* gAh = MHh + (long)(b * MROWS + lrow) * EMBD + ko0 + lseg;
            const __nv_bfloat16* gAl = MHl + (long)(b * MROWS + lrow) * EMBD + ko0 + lseg;
            const __nv_bfloat16* gBh = Xh + (long)(b * TTOK + col0 + lrow) * EMBD + ko0 + lseg;
            const __nv_bfloat16* gBl = Xl + (long)(b * TTOK + col0 + lrow) * EMBD + ko0 + lseg;
            char* sAh = smem + OFF_AH + lrow * (PADK * 2) + lseg * 2;
            char* sAl = smem + OFF_AL + lrow * (PADK * 2) + lseg * 2;
            char* sBh = smem + OFF_BH + lrow * (PADK * 2) + lseg * 2;
            char* sBl = smem + OFF_BL + lrow * (PADK * 2) + lseg * 2;
            #pragma unroll
            for (int j = 0; j < 4; j++) {
                *(uint4*)(sAh + j * 16) = *(const uint4*)(gAh + j * 8);
                *(uint4*)(sAl + j * 16) = *(const uint4*)(gAl + j * 8);
                *(uint4*)(sBh + j * 16) = *(const uint4*)(gBh + j * 8);
                *(uint4*)(sBl + j * 16) = *(const uint4*)(gBl + j * 8);
            }
        }
        __syncthreads();

        #pragma unroll
        for (int ks = 0; ks < 4; ks++) {
            const int ko = ks * 16;
            uint32_t ahf[2][4], alf[2][4];
            #pragma unroll
            for (int mt = 0; mt < 2; mt++) {
                const int r0 = wm * 32 + mt * 16 + g;
                const char* bAh = smem + OFF_AH;
                const char* bAl = smem + OFF_AL;
                const int c0 = (ko + 2 * tig) * 2;
                const int c8 = (ko + 8 + 2 * tig) * 2;
                ahf[mt][0] = *(const uint32_t*)(bAh + r0 * (PADK*2) + c0);
                ahf[mt][1] = *(const uint32_t*)(bAh + (r0+8) * (PADK*2) + c0);
                ahf[mt][2] = *(const uint32_t*)(bAh + r0 * (PADK*2) + c8);
                ahf[mt][3] = *(const uint32_t*)(bAh + (r0+8) * (PADK*2) + c8);
                alf[mt][0] = *(const uint32_t*)(bAl + r0 * (PADK*2) + c0);
                alf[mt][1] = *(const uint32_t*)(bAl + (r0+8) * (PADK*2) + c0);
                alf[mt][2] = *(const uint32_t*)(bAl + r0 * (PADK*2) + c8);
                alf[mt][3] = *(const uint32_t*)(bAl + (r0+8) * (PADK*2) + c8);
            }
            #pragma unroll
            for (int nt = 0; nt < 8; nt++) {
                const int nr = wn * 64 + nt * 8 + g;
                const char* bBh = smem + OFF_BH;
                const char* bBl = smem + OFF_BL;
                const int c0 = (ko + 2 * tig) * 2;
                const int c8 = (ko + 8 + 2 * tig) * 2;
                const uint32_t bh0 = *(const uint32_t*)(bBh + nr * (PADK*2) + c0);
                const uint32_t bh1 = *(const uint32_t*)(bBh + nr * (PADK*2) + c8);
                const uint32_t bl0 = *(const uint32_t*)(bBl + nr * (PADK*2) + c0);
                const uint32_t bl1 = *(const uint32_t*)(bBl + nr * (PADK*2) + c8);
                #pragma unroll
                for (int mt = 0; mt < 2; mt++) {
                    mma_bf16(acc[mt][nt], ahf[mt], bh0, bh1);
                    mma_bf16(acc[mt][nt], ahf[mt], bl0, bl1);
                    mma_bf16(acc[mt][nt], alf[mt], bh0, bh1);
                }
            }
        }
        __syncthreads();
    }

    float lsum = 0.0f;
    #pragma unroll
    for (int mt = 0; mt < 2; mt++) {
        const int r_lo = wm * 32 + mt * 16 + g;
        const int r_hi = r_lo + 8;
        const long base_lo = (long)b * OUT_PER_B + (long)r_lo * TTOK;
        const long base_hi = (long)b * OUT_PER_B + (long)r_hi * TTOK;
        #pragma unroll
        for (int nt = 0; nt < 8; nt++) {
            const int t = col0 + wn * 64 + nt * 8 + 2 * tig;
            const float y0 = __expf(10.0f * tanh_fast(acc[mt][nt][0] * 0.0625f) + mask[base_lo + t]);
            const float y1 = __expf(10.0f * tanh_fast(acc[mt][nt][1] * 0.0625f) + mask[base_lo + t + 1]);
            const float y2 = __expf(10.0f * tanh_fast(acc[mt][nt][2] * 0.0625f) + mask[base_hi + t]);
            const float y3 = __expf(10.0f * tanh_fast(acc[mt][nt][3] * 0.0625f) + mask[base_hi + t + 1]);
            out[base_lo + t]     = y0;
            out[base_lo + t + 1] = y1;
            out[base_hi + t]     = y2;
            out[base_hi + t + 1] = y3;
            lsum += y0 + y1 + y2 + y3;
        }
    }

    red[tid] = lsum;
    __syncthreads();
    #pragma unroll
    for (int s = 128; s > 0; s >>= 1) {
        if (tid < s) red[tid] += red[tid + s];
        __syncthreads();
    }
    if (tid == 0) atomicAdd(&sums[b], red[0]);
}

// =================== t=512 column tail ================
__global__ void __launch_bounds__(128)
tail_kernel(const float* __restrict__ MH, const float* __restrict__ jobs,
            const float* __restrict__ mask, float* __restrict__ out,
            float* __restrict__ sums)
{
    __shared__ float jrow[EMBD];
    __shared__ float red[128];

    const int b = blockIdx.x;
    const int m = threadIdx.x;

    const float* jr = jobs + ((long)b * JJOBS + 511) * EMBD;
    *(float2*)&jrow[m * 2] = *(const float2*)(jr + m * 2);
    __syncthreads();

    const float* mh = MH + ((long)b * MROWS + m) * EMBD;
    ull d2 = bcast2(0.0f);
    #pragma unroll
    for (int k = 0; k < EMBD; k += 8) {
        ulonglong2 a = *(const ulonglong2*)(mh + k);
        ulonglong2 a2 = *(const ulonglong2*)(mh + k + 4);
        ulonglong2 w = *(const ulonglong2*)&jrow[k];
        ulonglong2 w2 = *(const ulonglong2*)&jrow[k + 4];
        d2 = fma2(a.x, w.x, d2);
        d2 = fma2(a.y, w.y, d2);
        d2 = fma2(a2.x, w2.x, d2);
        d2 = fma2(a2.y, w2.y, d2);
    }
    float2 f = unpack2(d2);
    const float sc = (f.x + f.y) * 0.0625f;
    const long li = (long)b * OUT_PER_B + (long)m * TTOK + 512;
    const float y = __expf(10.0f * tanh_fast(sc) + mask[li]);
    out[li] = y;

    red[m] = y;
    __syncthreads();
    #pragma unroll
    for (int s = 64; s > 0; s >>= 1) {
        if (m < s) red[m] += red[m + s];
        __syncthreads();
    }
    if (m == 0) atomicAdd(&sums[b], red[0]);
}

// =================== normalize =======================
__global__ void __launch_bounds__(256)
norm_kernel(float4* __restrict__ out, const float* __restrict__ sums)
{
    const int b = blockIdx.y;
    const long per_b4 = OUT_PER_B / 4;
    const long idx = (long)blockIdx.x * blockDim.x + threadIdx.x;
    if (idx < per_b4) {
        const float inv = 1.0f / sums[b];
        float4 v = out[(long)b * per_b4 + idx];
        v.x *= inv; v.y *= inv; v.z *= inv; v.w *= inv;
        out[(long)b * per_b4 + idx] = v;
    }
}

// =================== launch ===================
extern "C" void kernel_launch(void* const* d_in, const int* in_sizes, int n_in,
                              void* d_out, int out_size)
{
    const float* machine = (const float*)d_in[0];
    const float* jobs    = (const float*)d_in[1];
    const float* mask    = (const float*)d_in[2];
    const float* Wq3     = (const float*)d_in[3];
    const float* Wk      = (const float*)d_in[4];
    const float* Wv      = (const float*)d_in[5];
    const float* Wc      = (const float*)d_in[6];
    const float* bc      = (const float*)d_in[7];
    const float* skip    = (const float*)d_in[8];
    float* out = (float*)d_out;

    float *Qp, *Kp, *Vp, *Op, *MHp, *Sp;
    __nv_bfloat16 *Xh, *Xl, *Wh, *Wl, *MHh, *MHl;
    cudaGetSymbolAddress((void**)&Qp,  g_Q);
    cudaGetSymbolAddress((void**)&Kp,  g_K);
    cudaGetSymbolAddress((void**)&Vp,  g_V);
    cudaGetSymbolAddress((void**)&Op,  g_O);
    cudaGetSymbolAddress((void**)&MHp, g_MH);
    cudaGetSymbolAddress((void**)&Sp,  g_SUM);
    cudaGetSymbolAddress((void**)&Xh,  g_Xh);
    cudaGetSymbolAddress((void**)&Xl,  g_Xl);
    cudaGetSymbolAddress((void**)&Wh,  g_Wh);
    cudaGetSymbolAddress((void**)&Wl,  g_Wl);
    cudaGetSymbolAddress((void**)&MHh, g_MHh);
    cudaGetSymbolAddress((void**)&MHl, g_MHl);

    cudaFuncSetAttribute(proj_wmma_kernel,
                         cudaFuncAttributeMaxDynamicSharedMemorySize, PROJ_SMEM);
    cudaFuncSetAttribute(score2_kernel,
                         cudaFuncAttributeMaxDynamicSharedMemorySize, PROJ_SMEM);

    convert_w_kernel<<<dim3(8, 8, 3), 256>>>(Wk, Wv, Wq3, Wh, Wl);
    {
        const long total = (long)XROWS * 32;
        convert_x_kernel<<<(int)((total + 255) / 256), 256>>>(
            jobs, skip, machine, Xh, Xl, Sp);
    }

    proj_wmma_kernel<<<dim3(2, 257, 3), 256, PROJ_SMEM>>>(
        Xh, Xl, Wh, Wl, Kp, Vp, Qp);

    attn_kernel<<<dim3(HEADS, BATCH), 128>>>(Qp, Kp, Vp, Op);

    wc_kernel<<<dim3(EMBD / BN, (BATCH * MROWS) / WBM), 256>>>(
        Op, Wc, bc, MHp, MHh, MHl);

    score2_kernel<<<dim3(4, 1, BATCH), 256, PROJ_SMEM>>>(
        MHh, MHl, Xh, Xl, mask, out, Sp);
    tail_kernel<<<BATCH, 128>>>(MHp, jobs, mask, out, Sp);

    const int per_b4 = OUT_PER_B / 4;
    norm_kernel<<<dim3((per_b4 + 255) / 256, BATCH), 256>>>((float4*)out, Sp);
}